// round 15
// baseline (speedup 1.0000x reference)
#include <cuda_runtime.h>
#include <cuda_bf16.h>
#include <cstdint>

#define NMAX 100000
#define EMAX 800000

typedef unsigned long long ull;

// ---------------- scratch (device globals; no runtime allocation) ------------
__device__ float4 g_h2  [NMAX * 6];        // [N,24] padded (23 + 1 zero)
__device__ float4 g_q1  [NMAX * 48];       // [N,192] fp32, PERMUTED positions
__device__ __nv_bfloat162 g_k1[NMAX * 96]; // [N,192] bf16; slot l+32jj = true ch (tc+2jj, tc+2jj+1)
__device__ float4 g_v1  [NMAX * 48];       // [N,192] fp32, PERMUTED positions
__device__ float4 g_acc1[NMAX * 48];       // skip, then conv1 out (pre-elu), TRUE order
__device__ float4 g_q2  [NMAX * 16];       // [N,64] fp32
__device__ float4 g_kv2 [NMAX * 32];       // [N,128]: k | v fp32 linear
__device__ float4 g_acc2[NMAX * 16];       // conv2 out (pre-elu)
// CSR scratch
__device__ int    g_deg   [NMAX];
__device__ int    g_part  [NMAX];
__device__ int    g_bsum  [512];
__device__ int    g_rowptr[NMAX];
__device__ int    g_cursor[NMAX];
__device__ float4 g_epack [EMAX * 2];      // per edge: (src_bits, ea0..ea2), (ea3..ea6)

__device__ __forceinline__ float eluf(float x) { return x > 0.f ? x : expm1f(x); }

// ---- f32x2 packed-math helpers ----------------------------------------------
__device__ __forceinline__ ull pk2(float lo, float hi) {
    ull r; asm("mov.b64 %0,{%1,%2};" : "=l"(r) : "f"(lo), "f"(hi)); return r;
}
__device__ __forceinline__ void upk2(ull v, float& lo, float& hi) {
    asm("mov.b64 {%0,%1},%2;" : "=f"(lo), "=f"(hi) : "l"(v));
}
__device__ __forceinline__ ull fma2(ull a, ull b, ull c) {
    ull d; asm("fma.rn.f32x2 %0,%1,%2,%3;" : "=l"(d) : "l"(a), "l"(b), "l"(c)); return d;
}
__device__ __forceinline__ void lds_v2u64(ull& a, ull& b, uint32_t addr) {
    asm volatile("ld.shared.v2.u64 {%0,%1},[%2];" : "=l"(a), "=l"(b) : "r"(addr));
}
__device__ __forceinline__ ull lds_u64(uint32_t addr) {
    ull a; asm volatile("ld.shared.b64 %0,[%1];" : "=l"(a) : "r"(addr)); return a;
}
__device__ __forceinline__ uint32_t smem_u32(const void* p) {
    uint32_t a;
    asm("{ .reg .u64 t; cvta.to.shared.u64 t, %1; cvt.u32.u64 %0, t; }" : "=r"(a) : "l"(p));
    return a;
}

// ---------------- CSR build ---------------------------------------------------
__global__ void k_zero(int n) {
    int i = blockIdx.x * blockDim.x + threadIdx.x;
    if (i < n) g_deg[i] = 0;
}
__global__ void k_count(const int* __restrict__ dst, int E) {
    int e = blockIdx.x * blockDim.x + threadIdx.x;
    if (e < E) atomicAdd(&g_deg[dst[e]], 1);
}
__global__ void k_scanA(int n) {                 // 256 threads/block
    __shared__ int s[256];
    int tid = threadIdx.x, i = blockIdx.x * 256 + tid;
    int v = (i < n) ? g_deg[i] : 0;
    s[tid] = v; __syncthreads();
    #pragma unroll
    for (int off = 1; off < 256; off <<= 1) {
        int t = (tid >= off) ? s[tid - off] : 0;
        __syncthreads();
        s[tid] += t;
        __syncthreads();
    }
    if (i < n) g_part[i] = s[tid] - v;           // exclusive within block
    if (tid == 255) g_bsum[blockIdx.x] = s[255];
}
__global__ void k_scanB(int nb) {                // single block, 512 threads
    __shared__ int s[512];
    int tid = threadIdx.x;
    int v = (tid < nb) ? g_bsum[tid] : 0;
    s[tid] = v; __syncthreads();
    #pragma unroll
    for (int off = 1; off < 512; off <<= 1) {
        int t = (tid >= off) ? s[tid - off] : 0;
        __syncthreads();
        s[tid] += t;
        __syncthreads();
    }
    g_bsum[tid] = s[tid] - v;                    // exclusive block offsets
}
__global__ void k_scanC(int n) {
    int i = blockIdx.x * blockDim.x + threadIdx.x;
    if (i < n) {
        int r = g_part[i] + g_bsum[i >> 8];
        g_rowptr[i] = r;
        g_cursor[i] = r;
    }
}
// Scatter + ea payload fold: per edge write (src, ea0..6) as two float4s.
__global__ void k_scatter(const int* __restrict__ src, const int* __restrict__ dst,
                          const float* __restrict__ ea, int E) {
    int e = blockIdx.x * blockDim.x + threadIdx.x;
    if (e < E) {
        int d = dst[e];
        int pos = atomicAdd(&g_cursor[d], 1);
        const float* ep = ea + (size_t)e * 7;
        float4 p0, p1;
        p0.x = __int_as_float(src[e]);
        p0.y = ep[0]; p0.z = ep[1]; p0.w = ep[2];
        p1.x = ep[3]; p1.y = ep[4]; p1.z = ep[5]; p1.w = ep[6];
        g_epack[2 * (size_t)pos]     = p0;
        g_epack[2 * (size_t)pos + 1] = p1;
    }
}

// ---------------- h2 = elu(elu(x@A+bA)@B+bB), padded to 24 -------------------
__global__ void k_h2(const float* __restrict__ x,
                     const float* __restrict__ Aw, const float* __restrict__ Ab,
                     const float* __restrict__ Bw, const float* __restrict__ Bb,
                     int n) {
    __shared__ float sA[23 * 23], sB[23 * 23], sbA[23], sbB[23];
    __shared__ float sx[256 * 23];
    int tid = threadIdx.x;
    for (int i = tid; i < 23 * 23; i += 256) { sA[i] = Aw[i]; sB[i] = Bw[i]; }
    if (tid < 23) { sbA[tid] = Ab[tid]; sbB[tid] = Bb[tid]; }
    int base = blockIdx.x * 256;
    int cnt  = min(256, n - base);
    for (int i = tid; i < cnt * 23; i += 256) sx[i] = x[(size_t)base * 23 + i];
    __syncthreads();
    if (tid < cnt) {
        const float* xr = &sx[tid * 23];
        float h1[23];
        #pragma unroll
        for (int j = 0; j < 23; j++) {
            float a = sbA[j];
            #pragma unroll
            for (int k = 0; k < 23; k++) a += xr[k] * sA[k * 23 + j];
            h1[j] = eluf(a);
        }
        float* out = (float*)g_h2 + (size_t)(base + tid) * 24;
        #pragma unroll
        for (int j = 0; j < 23; j++) {
            float a = sbB[j];
            #pragma unroll
            for (int k = 0; k < 23; k++) a += h1[k] * sB[k * 23 + j];
            out[j] = eluf(a);
        }
        out[23] = 0.f;
    }
}

// ---------------- conv1 node GEMM: [N,24]@[24,768], f32x2, C=2 ---------------
// __launch_bounds__(384,2): profiler-verified win (133.7 -> ~122 us).
__global__ __launch_bounds__(384, 2) void k_gemm1(
        const float* __restrict__ qw, const float* __restrict__ qb,
        const float* __restrict__ kw, const float* __restrict__ kb,
        const float* __restrict__ vw, const float* __restrict__ vb,
        const float* __restrict__ sw, const float* __restrict__ sb,
        int n) {
    __shared__ float sT[24 * 128];          // transposed [k][node]
    int tid = threadIdx.x;                  // 384 threads
    int base = blockIdx.x * 128;
    int cnt  = min(128, n - base);
    for (int i = tid; i < 768; i += 384) {
        int nn = i & 127, k4 = i >> 7;      // k4 in 0..5
        float4 v = (nn < cnt) ? g_h2[(size_t)(base + nn) * 6 + k4] : make_float4(0, 0, 0, 0);
        sT[(4 * k4 + 0) * 128 + nn] = v.x;
        sT[(4 * k4 + 1) * 128 + nn] = v.y;
        sT[(4 * k4 + 2) * 128 + nn] = v.z;
        sT[(4 * k4 + 3) * 128 + nn] = v.w;
    }
    __syncthreads();
    int arr = tid / 96, pp = tid % 96;
    int l = pp & 31, jj = pp >> 5;
    int p0 = l + 64 * jj, p1 = p0 + 32;
    int cc0, cc1;
    if (arr <= 2) {
        int tc = (l >> 2) * 24 + (l & 3) * 6;
        cc0 = tc + 2 * jj; cc1 = cc0 + 1;
    } else { cc0 = p0; cc1 = p1; }
    const float* W = arr == 0 ? qw : arr == 1 ? kw : arr == 2 ? vw : sw;
    const float* B = arr == 0 ? qb : arr == 1 ? kb : arr == 2 ? vb : sb;
    float* op = arr == 0 ? (float*)g_q1 : arr == 2 ? (float*)g_v1 : (float*)g_acc1;
    int kslot = l + 32 * jj;
    float w0[23], w1[23];
    #pragma unroll
    for (int k = 0; k < 23; k++) { w0[k] = W[k * 192 + cc0]; w1[k] = W[k * 192 + cc1]; }
    float bias0 = B[cc0], bias1 = B[cc1];
    uint32_t sbase = smem_u32(sT);
    for (int ch = 0; ch < 8; ch++) {
        int n0 = ch * 16;
        ull a0[8], a1[8];
        ull b20 = pk2(bias0, bias0), b21 = pk2(bias1, bias1);
        #pragma unroll
        for (int q8 = 0; q8 < 8; q8++) { a0[q8] = b20; a1[q8] = b21; }
        #pragma unroll
        for (int k = 0; k < 23; k++) {
            ull w20 = pk2(w0[k], w0[k]);
            ull w21 = pk2(w1[k], w1[k]);
            uint32_t ra = sbase + (uint32_t)(k * 128 + n0) * 4u;
            #pragma unroll
            for (int q4 = 0; q4 < 4; q4++) {
                ull h01, h23;
                lds_v2u64(h01, h23, ra + 16u * q4);
                a0[2 * q4]     = fma2(h01, w20, a0[2 * q4]);
                a0[2 * q4 + 1] = fma2(h23, w20, a0[2 * q4 + 1]);
                a1[2 * q4]     = fma2(h01, w21, a1[2 * q4]);
                a1[2 * q4 + 1] = fma2(h23, w21, a1[2 * q4 + 1]);
            }
        }
        #pragma unroll
        for (int q8 = 0; q8 < 8; q8++) {
            float lo0, hi0, lo1, hi1;
            upk2(a0[q8], lo0, hi0);
            upk2(a1[q8], lo1, hi1);
            int na = n0 + 2 * q8, nb = na + 1;
            if (arr == 1) {
                __nv_bfloat162 ta; ta.x = __float2bfloat16(lo0); ta.y = __float2bfloat16(lo1);
                __nv_bfloat162 tb; tb.x = __float2bfloat16(hi0); tb.y = __float2bfloat16(hi1);
                if (na < cnt) g_k1[(size_t)(base + na) * 96 + kslot] = ta;
                if (nb < cnt) g_k1[(size_t)(base + nb) * 96 + kslot] = tb;
            } else {
                if (na < cnt) {
                    op[(size_t)(base + na) * 192 + p0] = lo0;
                    op[(size_t)(base + na) * 192 + p1] = lo1;
                }
                if (nb < cnt) {
                    op[(size_t)(base + nb) * 192 + p0] = hi0;
                    op[(size_t)(base + nb) * 192 + p1] = hi1;
                }
            }
        }
    }
}

// ---------------- conv1: node-centric fused softmax-aggregate -----------------
// Edge payload (src + ea) read as two broadcast LDG.128 from streamed g_epack.
__global__ void k_conv1(const float* __restrict__ ew, int n) {
    __shared__ float sW[1344];              // e1_w [7,192] true order
    int tid = threadIdx.x;
    for (int i = tid; i < 1344; i += 256) sW[i] = ew[i];
    __syncthreads();
    int node = blockIdx.x * 8 + (tid >> 5);
    int lane = tid & 31;
    if (node >= n) return;
    int deg = g_deg[node];
    if (deg == 0) return;                   // acc1 already holds skip
    int rs = g_rowptr[node];
    int g = lane & 3;
    int tc = (lane >> 2) * 24 + g * 6;      // true channel base (<= 186)

    const float* qf = (const float*)g_q1 + (size_t)node * 192 + lane;
    float q0 = qf[0],  q1 = qf[32],  q2 = qf[64],
          q3 = qf[96], q4 = qf[128], q5 = qf[160];

    float pqh[7];
    #pragma unroll
    for (int t = 0; t < 7; t++) {
        const float* w = &sW[t * 192 + tc];
        float p = q0 * w[0] + q1 * w[1] + q2 * w[2] + q3 * w[3] + q4 * w[4] + q5 * w[5];
        p += __shfl_xor_sync(0xffffffffu, p, 1);
        p += __shfl_xor_sync(0xffffffffu, p, 2);
        pqh[t] = p;
    }

    float acc0 = 0.f, acc1 = 0.f, acc2 = 0.f, acc3 = 0.f, acc4 = 0.f, acc5 = 0.f;
    float den = 0.f, a0 = 0.f, a1 = 0.f;

    for (int i = 0; i < deg; i++) {
        float4 p0 = g_epack[2 * (size_t)(rs + i)];
        float4 p1 = g_epack[2 * (size_t)(rs + i) + 1];
        int s = __float_as_int(p0.x);
        float eav[7] = {p0.y, p0.z, p0.w, p1.x, p1.y, p1.z, p1.w};
        const __nv_bfloat162* kb = g_k1 + (size_t)s * 96 + lane;
        float2 k01 = __bfloat1622float2(kb[0]);
        float2 k23 = __bfloat1622float2(kb[32]);
        float2 k45 = __bfloat1622float2(kb[64]);
        const float* vf = (const float*)g_v1 + (size_t)s * 192 + lane;
        float v0 = vf[0],  v1 = vf[32],  v2 = vf[64],
              v3 = vf[96], v4 = vf[128], v5 = vf[160];
        float lp = q0 * k01.x + q1 * k01.y + q2 * k23.x
                 + q3 * k23.y + q4 * k45.x + q5 * k45.y;
        lp += __shfl_xor_sync(0xffffffffu, lp, 1);
        lp += __shfl_xor_sync(0xffffffffu, lp, 2);
        #pragma unroll
        for (int t = 0; t < 7; t++) lp += eav[t] * pqh[t];
        float ex = __expf(lp * 0.20412414523193154f);   // 1/sqrt(24)
        den += ex;
        acc0 += ex * v0; acc1 += ex * v1; acc2 += ex * v2;
        acc3 += ex * v3; acc4 += ex * v4; acc5 += ex * v5;
        float elo = g == 0 ? eav[0] : g == 1 ? eav[2] : g == 2 ? eav[4] : eav[6];
        float ehi = g == 0 ? eav[1] : g == 1 ? eav[3] : g == 2 ? eav[5] : 0.f;
        a0 += ex * elo;
        a1 += ex * ehi;
    }

    float inv = 1.f / den;
    int base = lane & ~3;
    float ae[7];
    ae[0] = __shfl_sync(0xffffffffu, a0, base);
    ae[1] = __shfl_sync(0xffffffffu, a1, base);
    ae[2] = __shfl_sync(0xffffffffu, a0, base + 1);
    ae[3] = __shfl_sync(0xffffffffu, a1, base + 1);
    ae[4] = __shfl_sync(0xffffffffu, a0, base + 2);
    ae[5] = __shfl_sync(0xffffffffu, a1, base + 2);
    ae[6] = __shfl_sync(0xffffffffu, a0, base + 3);

    float m[6] = {acc0, acc1, acc2, acc3, acc4, acc5};
    const float* wb = &sW[tc];
    #pragma unroll
    for (int j = 0; j < 6; j++) {
        #pragma unroll
        for (int t = 0; t < 7; t++) m[j] += ae[t] * wb[t * 192 + j];
    }
    float* outp = (float*)g_acc1 + (size_t)node * 192 + tc;
    #pragma unroll
    for (int j2 = 0; j2 < 3; j2++) {
        float2 sk = *(float2*)(outp + 2 * j2);
        sk.x += m[2 * j2] * inv;
        sk.y += m[2 * j2 + 1] * inv;
        *(float2*)(outp + 2 * j2) = sk;
    }
}

// ---------------- conv2 node GEMM: elu(acc1) [N,192]@[192,256], f32x2, C=4 ---
__global__ __launch_bounds__(256) void k_gemm2(
        const float* __restrict__ qw, const float* __restrict__ qb,
        const float* __restrict__ kw, const float* __restrict__ kb,
        const float* __restrict__ vw, const float* __restrict__ vb,
        const float* __restrict__ sw, const float* __restrict__ sb,
        int n) {
    __shared__ float sT[192 * 68];          // transposed [k][node], pad 68
    int tid = threadIdx.x;                  // 256 threads
    int base = blockIdx.x * 64;
    int cnt  = min(64, n - base);
    for (int i = tid; i < 64 * 48; i += 256) {
        int nn = i / 48, k4 = i % 48;
        float4 v = (nn < cnt) ? g_acc1[(size_t)(base + nn) * 48 + k4] : make_float4(0, 0, 0, 0);
        v.x = eluf(v.x); v.y = eluf(v.y); v.z = eluf(v.z); v.w = eluf(v.w);
        sT[(4 * k4 + 0) * 68 + nn] = v.x;
        sT[(4 * k4 + 1) * 68 + nn] = v.y;
        sT[(4 * k4 + 2) * 68 + nn] = v.z;
        sT[(4 * k4 + 3) * 68 + nn] = v.w;
    }
    __syncthreads();
    int arr = tid >> 6, u = tid & 63;
    int cq = u & 15, nh = u >> 4;           // nh 0..3 -> nodes nh*16..nh*16+15
    int c0 = 4 * cq;
    const float* W = arr == 0 ? qw : arr == 1 ? kw : arr == 2 ? vw : sw;
    const float* B = arr == 0 ? qb : arr == 1 ? kb : arr == 2 ? vb : sb;
    float* op; int stride; int coff;
    if (arr == 0)      { op = (float*)g_q2;  stride = 64;  coff = c0; }
    else if (arr == 1) { op = (float*)g_kv2; stride = 128; coff = c0; }
    else if (arr == 2) { op = (float*)g_kv2; stride = 128; coff = 64 + c0; }
    else               { op = (float*)g_acc2; stride = 64; coff = c0; }
    ull acc[4][8];
    #pragma unroll
    for (int c = 0; c < 4; c++) {
        float bb = B[c0 + c];
        ull b2 = pk2(bb, bb);
        #pragma unroll
        for (int p = 0; p < 8; p++) acc[c][p] = b2;
    }
    uint32_t sbase = smem_u32(sT);
    #pragma unroll 2
    for (int k = 0; k < 192; k++) {
        float4 w4 = *(const float4*)&W[k * 64 + c0];
        ull w20 = pk2(w4.x, w4.x), w21 = pk2(w4.y, w4.y);
        ull w22 = pk2(w4.z, w4.z), w23 = pk2(w4.w, w4.w);
        uint32_t ra = sbase + (uint32_t)(k * 68 + nh * 16) * 4u;
        ull h[8];
        lds_v2u64(h[0], h[1], ra);
        lds_v2u64(h[2], h[3], ra + 16u);
        lds_v2u64(h[4], h[5], ra + 32u);
        lds_v2u64(h[6], h[7], ra + 48u);
        #pragma unroll
        for (int p = 0; p < 8; p++) {
            acc[0][p] = fma2(h[p], w20, acc[0][p]);
            acc[1][p] = fma2(h[p], w21, acc[1][p]);
            acc[2][p] = fma2(h[p], w22, acc[2][p]);
            acc[3][p] = fma2(h[p], w23, acc[3][p]);
        }
    }
    #pragma unroll
    for (int c = 0; c < 4; c++) {
        #pragma unroll
        for (int p = 0; p < 8; p++) {
            float lo, hi; upk2(acc[c][p], lo, hi);
            int na = nh * 16 + 2 * p, nb = na + 1;
            if (na < cnt) op[(size_t)(base + na) * stride + coff + c] = lo;
            if (nb < cnt) op[(size_t)(base + nb) * stride + coff + c] = hi;
        }
    }
}

// ---------------- conv2: node-centric fused softmax-aggregate -----------------
__global__ void k_conv2(const float* __restrict__ ew, int n) {
    __shared__ float sW[448];               // e2_w [7,64]
    int tid = threadIdx.x;
    for (int i = tid; i < 448; i += 256) sW[i] = ew[i];
    __syncthreads();
    int node = blockIdx.x * 8 + (tid >> 5);
    int lane = tid & 31;
    if (node >= n) return;
    int deg = g_deg[node];
    if (deg == 0) return;
    int rs = g_rowptr[node];

    const float* qr = (const float*)g_q2 + (size_t)node * 64 + lane * 2;
    float2 qv = *(const float2*)qr;

    float pqh[7];
    #pragma unroll
    for (int t = 0; t < 7; t++) {
        const float* w = &sW[t * 64 + lane * 2];
        float p = qv.x * w[0] + qv.y * w[1];
        p += __shfl_xor_sync(0xffffffffu, p, 1);
        p += __shfl_xor_sync(0xffffffffu, p, 2);
        pqh[t] = p;
    }

    float acc0 = 0.f, acc1 = 0.f, den = 0.f, a0 = 0.f, a1 = 0.f;
    int g = lane & 3;

    for (int i = 0; i < deg; i++) {
        float4 p0 = g_epack[2 * (size_t)(rs + i)];
        float4 p1 = g_epack[2 * (size_t)(rs + i) + 1];
        int s = __float_as_int(p0.x);
        float eav[7] = {p0.y, p0.z, p0.w, p1.x, p1.y, p1.z, p1.w};
        const float* kv = (const float*)g_kv2 + (size_t)s * 128 + lane * 2;
        float2 kk = *(const float2*)kv;
        float2 vv = *(const float2*)(kv + 64);
        float lp = qv.x * kk.x + qv.y * kk.y;
        lp += __shfl_xor_sync(0xffffffffu, lp, 1);
        lp += __shfl_xor_sync(0xffffffffu, lp, 2);
        #pragma unroll
        for (int t = 0; t < 7; t++) lp += eav[t] * pqh[t];
        float ex = __expf(lp * 0.35355339059327373f);   // 1/sqrt(8)
        den += ex;
        acc0 += ex * vv.x;
        acc1 += ex * vv.y;
        float elo = g == 0 ? eav[0] : g == 1 ? eav[2] : g == 2 ? eav[4] : eav[6];
        float ehi = g == 0 ? eav[1] : g == 1 ? eav[3] : g == 2 ? eav[5] : 0.f;
        a0 += ex * elo;
        a1 += ex * ehi;
    }

    float inv = 1.f / den;
    int base = lane & ~3;
    float ae[7];
    ae[0] = __shfl_sync(0xffffffffu, a0, base);
    ae[1] = __shfl_sync(0xffffffffu, a1, base);
    ae[2] = __shfl_sync(0xffffffffu, a0, base + 1);
    ae[3] = __shfl_sync(0xffffffffu, a1, base + 1);
    ae[4] = __shfl_sync(0xffffffffu, a0, base + 2);
    ae[5] = __shfl_sync(0xffffffffu, a1, base + 2);
    ae[6] = __shfl_sync(0xffffffffu, a0, base + 3);

    float m0 = acc0, m1 = acc1;
    const float* wb = &sW[lane * 2];
    #pragma unroll
    for (int t = 0; t < 7; t++) {
        m0 += ae[t] * wb[t * 64];
        m1 += ae[t] * wb[t * 64 + 1];
    }
    float* outp = (float*)g_acc2 + (size_t)node * 64 + lane * 2;
    float2 sk = *(float2*)outp;
    sk.x += m0 * inv;
    sk.y += m1 * inv;
    *(float2*)outp = sk;
}

// ---------------- head: elu -> lin1(64,20) -> elu -> lin2(20,1), f32x2 -------
__global__ void k_final(const float* __restrict__ w1, const float* __restrict__ b1,
                        const float* __restrict__ w2, const float* __restrict__ b2,
                        float* __restrict__ out, int n) {
    __shared__ float sw1t[20 * 64];         // transposed [j][k]
    __shared__ float sb1[20], sw2[20], sb2v[1];
    int tid = threadIdx.x;
    for (int i = tid; i < 1280; i += 256) {
        int k = i / 20, j = i % 20;
        sw1t[j * 64 + k] = w1[i];
    }
    if (tid < 20) { sb1[tid] = b1[tid]; sw2[tid] = w2[tid]; }
    if (tid == 0) sb2v[0] = b2[0];
    __syncthreads();
    int node = blockIdx.x * 256 + tid;
    if (node >= n) return;
    ull hp[32];
    const float4* r = g_acc2 + (size_t)node * 16;
    #pragma unroll
    for (int i = 0; i < 16; i++) {
        float4 v = r[i];
        hp[2 * i]     = pk2(eluf(v.x), eluf(v.y));
        hp[2 * i + 1] = pk2(eluf(v.z), eluf(v.w));
    }
    uint32_t sbase = smem_u32(sw1t);
    float res = sb2v[0];
    #pragma unroll 2
    for (int j = 0; j < 20; j++) {
        ull a2 = 0;
        uint32_t ra = sbase + (uint32_t)j * 256u;
        #pragma unroll
        for (int kk = 0; kk < 32; kk++) {
            ull w2p = lds_u64(ra + 8u * kk);
            a2 = fma2(hp[kk], w2p, a2);
        }
        float lo, hi; upk2(a2, lo, hi);
        res += eluf(sb1[j] + lo + hi) * sw2[j];
    }
    out[node] = res;
}

// ---------------- host launcher ----------------------------------------------
extern "C" void kernel_launch(void* const* d_in, const int* in_sizes, int n_in,
                              void* d_out, int out_size) {
    const float* x      = (const float*)d_in[0];
    const int*   ei     = (const int*)  d_in[1];
    const float* ea     = (const float*)d_in[2];
    const float* linA_w = (const float*)d_in[3];
    const float* linA_b = (const float*)d_in[4];
    const float* linB_w = (const float*)d_in[5];
    const float* linB_b = (const float*)d_in[6];
    const float* q1_w   = (const float*)d_in[7];
    const float* q1_b   = (const float*)d_in[8];
    const float* k1_w   = (const float*)d_in[9];
    const float* k1_b   = (const float*)d_in[10];
    const float* v1_w   = (const float*)d_in[11];
    const float* v1_b   = (const float*)d_in[12];
    const float* e1_w   = (const float*)d_in[13];
    const float* s1_w   = (const float*)d_in[14];
    const float* s1_b   = (const float*)d_in[15];
    const float* q2_w   = (const float*)d_in[16];
    const float* q2_b   = (const float*)d_in[17];
    const float* k2_w   = (const float*)d_in[18];
    const float* k2_b   = (const float*)d_in[19];
    const float* v2_w   = (const float*)d_in[20];
    const float* v2_b   = (const float*)d_in[21];
    const float* e2_w   = (const float*)d_in[22];
    const float* s2_w   = (const float*)d_in[23];
    const float* s2_b   = (const float*)d_in[24];
    const float* lin1_w = (const float*)d_in[25];
    const float* lin1_b = (const float*)d_in[26];
    const float* lin2_w = (const float*)d_in[27];
    const float* lin2_b = (const float*)d_in[28];

    int n = in_sizes[0] / 23;
    int E = in_sizes[1] / 2;
    const int* src = ei;
    const int* dst = ei + E;
    float* out = (float*)d_out;

    int nb256  = (n + 255) / 256;
    int eb256  = (E + 255) / 256;
    int nbconv = (n + 7) / 8;

    // EXACT R14 launch order (963 us best). k_gemm1 at launch index 3.
    k_zero   <<<nb256, 256>>>(n);
    k_count  <<<eb256, 256>>>(dst, E);
    k_h2     <<<nb256, 256>>>(x, linA_w, linA_b, linB_w, linB_b, n);
    k_gemm1  <<<(n + 127) / 128, 384>>>(q1_w, q1_b, k1_w, k1_b, v1_w, v1_b, s1_w, s1_b, n);
    k_scanA  <<<nb256, 256>>>(n);
    k_scanB  <<<1, 512>>>(nb256);
    k_scanC  <<<nb256, 256>>>(n);
    k_scatter<<<eb256, 256>>>(src, dst, ea, E);
    k_conv1  <<<nbconv, 256>>>(e1_w, n);
    k_gemm2  <<<(n + 63) / 64, 256>>>(q2_w, q2_b, k2_w, k2_b, v2_w, v2_b, s2_w, s2_b, n);
    k_conv2  <<<nbconv, 256>>>(e2_w, n);
    k_final  <<<nb256, 256>>>(lin1_w, lin1_b, lin2_w, lin2_b, out, n);
}

// round 16
// speedup vs baseline: 1.2073x; 1.2073x over previous
#include <cuda_runtime.h>
#include <cuda_bf16.h>
#include <cstdint>

#define NMAX 100000
#define EMAX 800000

typedef unsigned long long ull;

// ---------------- scratch (device globals; no runtime allocation) ------------
__device__ float4 g_h2  [NMAX * 6];        // [N,24] padded (23 + 1 zero)
__device__ float4 g_q1  [NMAX * 48];       // [N,192] fp32, PERMUTED positions
__device__ __nv_bfloat162 g_k1[NMAX * 96]; // [N,192] bf16; slot l+32jj = true ch (tc+2jj, tc+2jj+1)
__device__ float4 g_v1  [NMAX * 48];       // [N,192] fp32, PERMUTED positions
__device__ float4 g_acc1[NMAX * 48];       // skip, then conv1 out (pre-elu), TRUE order
__device__ float4 g_q2  [NMAX * 16];       // [N,64] fp32
__device__ float4 g_kv2 [NMAX * 32];       // [N,128]: k | v fp32 linear
__device__ float4 g_acc2[NMAX * 16];       // conv2 out (pre-elu)
// CSR scratch
__device__ int  g_deg   [NMAX];
__device__ int  g_part  [NMAX];
__device__ int  g_bsum  [512];
__device__ int  g_rowptr[NMAX];
__device__ int  g_cursor[NMAX];
__device__ int2 g_cpack [EMAX];            // (src, edge_id) grouped by dst

__device__ __forceinline__ float eluf(float x) { return x > 0.f ? x : expm1f(x); }

// ---- f32x2 packed-math helpers ----------------------------------------------
__device__ __forceinline__ ull pk2(float lo, float hi) {
    ull r; asm("mov.b64 %0,{%1,%2};" : "=l"(r) : "f"(lo), "f"(hi)); return r;
}
__device__ __forceinline__ void upk2(ull v, float& lo, float& hi) {
    asm("mov.b64 {%0,%1},%2;" : "=f"(lo), "=f"(hi) : "l"(v));
}
__device__ __forceinline__ ull fma2(ull a, ull b, ull c) {
    ull d; asm("fma.rn.f32x2 %0,%1,%2,%3;" : "=l"(d) : "l"(a), "l"(b), "l"(c)); return d;
}
__device__ __forceinline__ void lds_v2u64(ull& a, ull& b, uint32_t addr) {
    asm volatile("ld.shared.v2.u64 {%0,%1},[%2];" : "=l"(a), "=l"(b) : "r"(addr));
}
__device__ __forceinline__ ull lds_u64(uint32_t addr) {
    ull a; asm volatile("ld.shared.b64 %0,[%1];" : "=l"(a) : "r"(addr)); return a;
}
__device__ __forceinline__ uint32_t smem_u32(const void* p) {
    uint32_t a;
    asm("{ .reg .u64 t; cvta.to.shared.u64 t, %1; cvt.u32.u64 %0, t; }" : "=r"(a) : "l"(p));
    return a;
}

// ---------------- CSR build ---------------------------------------------------
__global__ void k_zero(int n) {
    int i = blockIdx.x * blockDim.x + threadIdx.x;
    if (i < n) g_deg[i] = 0;
}
__global__ void k_count(const int* __restrict__ dst, int E) {
    int e = blockIdx.x * blockDim.x + threadIdx.x;
    if (e < E) atomicAdd(&g_deg[dst[e]], 1);
}
__global__ void k_scanA(int n) {                 // 256 threads/block
    __shared__ int s[256];
    int tid = threadIdx.x, i = blockIdx.x * 256 + tid;
    int v = (i < n) ? g_deg[i] : 0;
    s[tid] = v; __syncthreads();
    #pragma unroll
    for (int off = 1; off < 256; off <<= 1) {
        int t = (tid >= off) ? s[tid - off] : 0;
        __syncthreads();
        s[tid] += t;
        __syncthreads();
    }
    if (i < n) g_part[i] = s[tid] - v;           // exclusive within block
    if (tid == 255) g_bsum[blockIdx.x] = s[255];
}
__global__ void k_scanB(int nb) {                // single block, 512 threads
    __shared__ int s[512];
    int tid = threadIdx.x;
    int v = (tid < nb) ? g_bsum[tid] : 0;
    s[tid] = v; __syncthreads();
    #pragma unroll
    for (int off = 1; off < 512; off <<= 1) {
        int t = (tid >= off) ? s[tid - off] : 0;
        __syncthreads();
        s[tid] += t;
        __syncthreads();
    }
    g_bsum[tid] = s[tid] - v;                    // exclusive block offsets
}
__global__ void k_scanC(int n) {
    int i = blockIdx.x * blockDim.x + threadIdx.x;
    if (i < n) {
        int r = g_part[i] + g_bsum[i >> 8];
        g_rowptr[i] = r;
        g_cursor[i] = r;
    }
}
__global__ void k_scatter(const int* __restrict__ src, const int* __restrict__ dst, int E) {
    int e = blockIdx.x * blockDim.x + threadIdx.x;
    if (e < E) {
        int d = dst[e];
        int pos = atomicAdd(&g_cursor[d], 1);
        g_cpack[pos] = make_int2(src[e], e);
    }
}

// ---------------- h2 = elu(elu(x@A+bA)@B+bB), padded to 24 -------------------
__global__ void k_h2(const float* __restrict__ x,
                     const float* __restrict__ Aw, const float* __restrict__ Ab,
                     const float* __restrict__ Bw, const float* __restrict__ Bb,
                     int n) {
    __shared__ float sA[23 * 23], sB[23 * 23], sbA[23], sbB[23];
    __shared__ float sx[256 * 23];
    int tid = threadIdx.x;
    for (int i = tid; i < 23 * 23; i += 256) { sA[i] = Aw[i]; sB[i] = Bw[i]; }
    if (tid < 23) { sbA[tid] = Ab[tid]; sbB[tid] = Bb[tid]; }
    int base = blockIdx.x * 256;
    int cnt  = min(256, n - base);
    for (int i = tid; i < cnt * 23; i += 256) sx[i] = x[(size_t)base * 23 + i];
    __syncthreads();
    if (tid < cnt) {
        const float* xr = &sx[tid * 23];
        float h1[23];
        #pragma unroll
        for (int j = 0; j < 23; j++) {
            float a = sbA[j];
            #pragma unroll
            for (int k = 0; k < 23; k++) a += xr[k] * sA[k * 23 + j];
            h1[j] = eluf(a);
        }
        float* out = (float*)g_h2 + (size_t)(base + tid) * 24;
        #pragma unroll
        for (int j = 0; j < 23; j++) {
            float a = sbB[j];
            #pragma unroll
            for (int k = 0; k < 23; k++) a += h1[k] * sB[k * 23 + j];
            out[j] = eluf(a);
        }
        out[23] = 0.f;
    }
}

// ---------------- conv1 node GEMM: [N,24]@[24,768], f32x2, C=2 ---------------
// __launch_bounds__(384,2): profiler-verified win (133.7 -> ~122 us, x3 sessions).
__global__ __launch_bounds__(384, 2) void k_gemm1(
        const float* __restrict__ qw, const float* __restrict__ qb,
        const float* __restrict__ kw, const float* __restrict__ kb,
        const float* __restrict__ vw, const float* __restrict__ vb,
        const float* __restrict__ sw, const float* __restrict__ sb,
        int n) {
    __shared__ float sT[24 * 128];          // transposed [k][node]
    int tid = threadIdx.x;                  // 384 threads
    int base = blockIdx.x * 128;
    int cnt  = min(128, n - base);
    for (int i = tid; i < 768; i += 384) {
        int nn = i & 127, k4 = i >> 7;      // k4 in 0..5
        float4 v = (nn < cnt) ? g_h2[(size_t)(base + nn) * 6 + k4] : make_float4(0, 0, 0, 0);
        sT[(4 * k4 + 0) * 128 + nn] = v.x;
        sT[(4 * k4 + 1) * 128 + nn] = v.y;
        sT[(4 * k4 + 2) * 128 + nn] = v.z;
        sT[(4 * k4 + 3) * 128 + nn] = v.w;
    }
    __syncthreads();
    int arr = tid / 96, pp = tid % 96;
    int l = pp & 31, jj = pp >> 5;
    int p0 = l + 64 * jj, p1 = p0 + 32;
    int cc0, cc1;
    if (arr <= 2) {
        int tc = (l >> 2) * 24 + (l & 3) * 6;
        cc0 = tc + 2 * jj; cc1 = cc0 + 1;
    } else { cc0 = p0; cc1 = p1; }
    const float* W = arr == 0 ? qw : arr == 1 ? kw : arr == 2 ? vw : sw;
    const float* B = arr == 0 ? qb : arr == 1 ? kb : arr == 2 ? vb : sb;
    float* op = arr == 0 ? (float*)g_q1 : arr == 2 ? (float*)g_v1 : (float*)g_acc1;
    int kslot = l + 32 * jj;
    float w0[23], w1[23];
    #pragma unroll
    for (int k = 0; k < 23; k++) { w0[k] = W[k * 192 + cc0]; w1[k] = W[k * 192 + cc1]; }
    float bias0 = B[cc0], bias1 = B[cc1];
    uint32_t sbase = smem_u32(sT);
    for (int ch = 0; ch < 8; ch++) {
        int n0 = ch * 16;
        ull a0[8], a1[8];
        ull b20 = pk2(bias0, bias0), b21 = pk2(bias1, bias1);
        #pragma unroll
        for (int q8 = 0; q8 < 8; q8++) { a0[q8] = b20; a1[q8] = b21; }
        #pragma unroll
        for (int k = 0; k < 23; k++) {
            ull w20 = pk2(w0[k], w0[k]);
            ull w21 = pk2(w1[k], w1[k]);
            uint32_t ra = sbase + (uint32_t)(k * 128 + n0) * 4u;
            #pragma unroll
            for (int q4 = 0; q4 < 4; q4++) {
                ull h01, h23;
                lds_v2u64(h01, h23, ra + 16u * q4);
                a0[2 * q4]     = fma2(h01, w20, a0[2 * q4]);
                a0[2 * q4 + 1] = fma2(h23, w20, a0[2 * q4 + 1]);
                a1[2 * q4]     = fma2(h01, w21, a1[2 * q4]);
                a1[2 * q4 + 1] = fma2(h23, w21, a1[2 * q4 + 1]);
            }
        }
        #pragma unroll
        for (int q8 = 0; q8 < 8; q8++) {
            float lo0, hi0, lo1, hi1;
            upk2(a0[q8], lo0, hi0);
            upk2(a1[q8], lo1, hi1);
            int na = n0 + 2 * q8, nb = na + 1;
            if (arr == 1) {
                __nv_bfloat162 ta; ta.x = __float2bfloat16(lo0); ta.y = __float2bfloat16(lo1);
                __nv_bfloat162 tb; tb.x = __float2bfloat16(hi0); tb.y = __float2bfloat16(hi1);
                if (na < cnt) g_k1[(size_t)(base + na) * 96 + kslot] = ta;
                if (nb < cnt) g_k1[(size_t)(base + nb) * 96 + kslot] = tb;
            } else {
                if (na < cnt) {
                    op[(size_t)(base + na) * 192 + p0] = lo0;
                    op[(size_t)(base + na) * 192 + p1] = lo1;
                }
                if (nb < cnt) {
                    op[(size_t)(base + nb) * 192 + p0] = hi0;
                    op[(size_t)(base + nb) * 192 + p1] = hi1;
                }
            }
        }
    }
}

// ---------------- conv1: node-centric fused softmax-aggregate (R9 proven) ----
__global__ void k_conv1(const float* __restrict__ ea, const float* __restrict__ ew, int n) {
    __shared__ float sW[1344];              // e1_w [7,192] true order
    int tid = threadIdx.x;
    for (int i = tid; i < 1344; i += 256) sW[i] = ew[i];
    __syncthreads();
    int node = blockIdx.x * 8 + (tid >> 5);
    int lane = tid & 31;
    if (node >= n) return;
    int deg = g_deg[node];
    if (deg == 0) return;                   // acc1 already holds skip
    int rs = g_rowptr[node];
    int g = lane & 3;
    int tc = (lane >> 2) * 24 + g * 6;      // true channel base (<= 186)

    const float* qf = (const float*)g_q1 + (size_t)node * 192 + lane;
    float q0 = qf[0],  q1 = qf[32],  q2 = qf[64],
          q3 = qf[96], q4 = qf[128], q5 = qf[160];

    float pqh[7];
    #pragma unroll
    for (int t = 0; t < 7; t++) {
        const float* w = &sW[t * 192 + tc];
        float p = q0 * w[0] + q1 * w[1] + q2 * w[2] + q3 * w[3] + q4 * w[4] + q5 * w[5];
        p += __shfl_xor_sync(0xffffffffu, p, 1);
        p += __shfl_xor_sync(0xffffffffu, p, 2);
        pqh[t] = p;
    }

    float acc0 = 0.f, acc1 = 0.f, acc2 = 0.f, acc3 = 0.f, acc4 = 0.f, acc5 = 0.f;
    float den = 0.f, a0 = 0.f, a1 = 0.f;

    int2 se = g_cpack[rs];
    for (int i = 0; i < deg; i++) {
        int s = se.x, eid = se.y;
        if (i + 1 < deg) se = g_cpack[rs + i + 1];
        float eav[7];
        #pragma unroll
        for (int t = 0; t < 7; t++) eav[t] = __ldg(&ea[(size_t)eid * 7 + t]);
        const __nv_bfloat162* kb = g_k1 + (size_t)s * 96 + lane;
        float2 k01 = __bfloat1622float2(kb[0]);
        float2 k23 = __bfloat1622float2(kb[32]);
        float2 k45 = __bfloat1622float2(kb[64]);
        const float* vf = (const float*)g_v1 + (size_t)s * 192 + lane;
        float v0 = vf[0],  v1 = vf[32],  v2 = vf[64],
              v3 = vf[96], v4 = vf[128], v5 = vf[160];
        float lp = q0 * k01.x + q1 * k01.y + q2 * k23.x
                 + q3 * k23.y + q4 * k45.x + q5 * k45.y;
        lp += __shfl_xor_sync(0xffffffffu, lp, 1);
        lp += __shfl_xor_sync(0xffffffffu, lp, 2);
        #pragma unroll
        for (int t = 0; t < 7; t++) lp += eav[t] * pqh[t];
        float ex = __expf(lp * 0.20412414523193154f);   // 1/sqrt(24)
        den += ex;
        acc0 += ex * v0; acc1 += ex * v1; acc2 += ex * v2;
        acc3 += ex * v3; acc4 += ex * v4; acc5 += ex * v5;
        float elo = g == 0 ? eav[0] : g == 1 ? eav[2] : g == 2 ? eav[4] : eav[6];
        float ehi = g == 0 ? eav[1] : g == 1 ? eav[3] : g == 2 ? eav[5] : 0.f;
        a0 += ex * elo;
        a1 += ex * ehi;
    }

    float inv = 1.f / den;
    int base = lane & ~3;
    float ae[7];
    ae[0] = __shfl_sync(0xffffffffu, a0, base);
    ae[1] = __shfl_sync(0xffffffffu, a1, base);
    ae[2] = __shfl_sync(0xffffffffu, a0, base + 1);
    ae[3] = __shfl_sync(0xffffffffu, a1, base + 1);
    ae[4] = __shfl_sync(0xffffffffu, a0, base + 2);
    ae[5] = __shfl_sync(0xffffffffu, a1, base + 2);
    ae[6] = __shfl_sync(0xffffffffu, a0, base + 3);

    float m[6] = {acc0, acc1, acc2, acc3, acc4, acc5};
    const float* wb = &sW[tc];
    #pragma unroll
    for (int j = 0; j < 6; j++) {
        #pragma unroll
        for (int t = 0; t < 7; t++) m[j] += ae[t] * wb[t * 192 + j];
    }
    float* outp = (float*)g_acc1 + (size_t)node * 192 + tc;
    #pragma unroll
    for (int j2 = 0; j2 < 3; j2++) {
        float2 sk = *(float2*)(outp + 2 * j2);
        sk.x += m[2 * j2] * inv;
        sk.y += m[2 * j2 + 1] * inv;
        *(float2*)(outp + 2 * j2) = sk;
    }
}

// ---------------- conv2 node GEMM: elu(acc1) [N,192]@[192,256], f32x2, C=4 ---
__global__ __launch_bounds__(256) void k_gemm2(
        const float* __restrict__ qw, const float* __restrict__ qb,
        const float* __restrict__ kw, const float* __restrict__ kb,
        const float* __restrict__ vw, const float* __restrict__ vb,
        const float* __restrict__ sw, const float* __restrict__ sb,
        int n) {
    __shared__ float sT[192 * 68];          // transposed [k][node], pad 68
    int tid = threadIdx.x;                  // 256 threads
    int base = blockIdx.x * 64;
    int cnt  = min(64, n - base);
    for (int i = tid; i < 64 * 48; i += 256) {
        int nn = i / 48, k4 = i % 48;
        float4 v = (nn < cnt) ? g_acc1[(size_t)(base + nn) * 48 + k4] : make_float4(0, 0, 0, 0);
        v.x = eluf(v.x); v.y = eluf(v.y); v.z = eluf(v.z); v.w = eluf(v.w);
        sT[(4 * k4 + 0) * 68 + nn] = v.x;
        sT[(4 * k4 + 1) * 68 + nn] = v.y;
        sT[(4 * k4 + 2) * 68 + nn] = v.z;
        sT[(4 * k4 + 3) * 68 + nn] = v.w;
    }
    __syncthreads();
    int arr = tid >> 6, u = tid & 63;
    int cq = u & 15, nh = u >> 4;           // nh 0..3 -> nodes nh*16..nh*16+15
    int c0 = 4 * cq;
    const float* W = arr == 0 ? qw : arr == 1 ? kw : arr == 2 ? vw : sw;
    const float* B = arr == 0 ? qb : arr == 1 ? kb : arr == 2 ? vb : sb;
    float* op; int stride; int coff;
    if (arr == 0)      { op = (float*)g_q2;  stride = 64;  coff = c0; }
    else if (arr == 1) { op = (float*)g_kv2; stride = 128; coff = c0; }
    else if (arr == 2) { op = (float*)g_kv2; stride = 128; coff = 64 + c0; }
    else               { op = (float*)g_acc2; stride = 64; coff = c0; }
    ull acc[4][8];
    #pragma unroll
    for (int c = 0; c < 4; c++) {
        float bb = B[c0 + c];
        ull b2 = pk2(bb, bb);
        #pragma unroll
        for (int p = 0; p < 8; p++) acc[c][p] = b2;
    }
    uint32_t sbase = smem_u32(sT);
    #pragma unroll 2
    for (int k = 0; k < 192; k++) {
        float4 w4 = *(const float4*)&W[k * 64 + c0];
        ull w20 = pk2(w4.x, w4.x), w21 = pk2(w4.y, w4.y);
        ull w22 = pk2(w4.z, w4.z), w23 = pk2(w4.w, w4.w);
        uint32_t ra = sbase + (uint32_t)(k * 68 + nh * 16) * 4u;
        ull h[8];
        lds_v2u64(h[0], h[1], ra);
        lds_v2u64(h[2], h[3], ra + 16u);
        lds_v2u64(h[4], h[5], ra + 32u);
        lds_v2u64(h[6], h[7], ra + 48u);
        #pragma unroll
        for (int p = 0; p < 8; p++) {
            acc[0][p] = fma2(h[p], w20, acc[0][p]);
            acc[1][p] = fma2(h[p], w21, acc[1][p]);
            acc[2][p] = fma2(h[p], w22, acc[2][p]);
            acc[3][p] = fma2(h[p], w23, acc[3][p]);
        }
    }
    #pragma unroll
    for (int c = 0; c < 4; c++) {
        #pragma unroll
        for (int p = 0; p < 8; p++) {
            float lo, hi; upk2(acc[c][p], lo, hi);
            int na = nh * 16 + 2 * p, nb = na + 1;
            if (na < cnt) op[(size_t)(base + na) * stride + coff + c] = lo;
            if (nb < cnt) op[(size_t)(base + nb) * stride + coff + c] = hi;
        }
    }
}

// ---------------- conv2: node-centric fused softmax-aggregate (R9 proven) ----
__global__ void k_conv2(const float* __restrict__ ea, const float* __restrict__ ew, int n) {
    __shared__ float sW[448];               // e2_w [7,64]
    int tid = threadIdx.x;
    for (int i = tid; i < 448; i += 256) sW[i] = ew[i];
    __syncthreads();
    int node = blockIdx.x * 8 + (tid >> 5);
    int lane = tid & 31;
    if (node >= n) return;
    int deg = g_deg[node];
    if (deg == 0) return;
    int rs = g_rowptr[node];

    const float* qr = (const float*)g_q2 + (size_t)node * 64 + lane * 2;
    float2 qv = *(const float2*)qr;

    float pqh[7];
    #pragma unroll
    for (int t = 0; t < 7; t++) {
        const float* w = &sW[t * 64 + lane * 2];
        float p = qv.x * w[0] + qv.y * w[1];
        p += __shfl_xor_sync(0xffffffffu, p, 1);
        p += __shfl_xor_sync(0xffffffffu, p, 2);
        pqh[t] = p;
    }

    float acc0 = 0.f, acc1 = 0.f, den = 0.f, a0 = 0.f, a1 = 0.f;
    int g = lane & 3;

    int2 se = g_cpack[rs];
    for (int i = 0; i < deg; i++) {
        int s = se.x, eid = se.y;
        if (i + 1 < deg) se = g_cpack[rs + i + 1];
        float eav[7];
        #pragma unroll
        for (int t = 0; t < 7; t++) eav[t] = __ldg(&ea[(size_t)eid * 7 + t]);
        const float* kv = (const float*)g_kv2 + (size_t)s * 128 + lane * 2;
        float2 kk = *(const float2*)kv;
        float2 vv = *(const float2*)(kv + 64);
        float lp = qv.x * kk.x + qv.y * kk.y;
        lp += __shfl_xor_sync(0xffffffffu, lp, 1);
        lp += __shfl_xor_sync(0xffffffffu, lp, 2);
        #pragma unroll
        for (int t = 0; t < 7; t++) lp += eav[t] * pqh[t];
        float ex = __expf(lp * 0.35355339059327373f);   // 1/sqrt(8)
        den += ex;
        acc0 += ex * vv.x;
        acc1 += ex * vv.y;
        float elo = g == 0 ? eav[0] : g == 1 ? eav[2] : g == 2 ? eav[4] : eav[6];
        float ehi = g == 0 ? eav[1] : g == 1 ? eav[3] : g == 2 ? eav[5] : 0.f;
        a0 += ex * elo;
        a1 += ex * ehi;
    }

    float inv = 1.f / den;
    int base = lane & ~3;
    float ae[7];
    ae[0] = __shfl_sync(0xffffffffu, a0, base);
    ae[1] = __shfl_sync(0xffffffffu, a1, base);
    ae[2] = __shfl_sync(0xffffffffu, a0, base + 1);
    ae[3] = __shfl_sync(0xffffffffu, a1, base + 1);
    ae[4] = __shfl_sync(0xffffffffu, a0, base + 2);
    ae[5] = __shfl_sync(0xffffffffu, a1, base + 2);
    ae[6] = __shfl_sync(0xffffffffu, a0, base + 3);

    float m0 = acc0, m1 = acc1;
    const float* wb = &sW[lane * 2];
    #pragma unroll
    for (int t = 0; t < 7; t++) {
        m0 += ae[t] * wb[t * 64];
        m1 += ae[t] * wb[t * 64 + 1];
    }
    float* outp = (float*)g_acc2 + (size_t)node * 64 + lane * 2;
    float2 sk = *(float2*)outp;
    sk.x += m0 * inv;
    sk.y += m1 * inv;
    *(float2*)outp = sk;
}

// ---------------- head: elu -> lin1(64,20) -> elu -> lin2(20,1), f32x2 -------
__global__ void k_final(const float* __restrict__ w1, const float* __restrict__ b1,
                        const float* __restrict__ w2, const float* __restrict__ b2,
                        float* __restrict__ out, int n) {
    __shared__ float sw1t[20 * 64];         // transposed [j][k]
    __shared__ float sb1[20], sw2[20], sb2v[1];
    int tid = threadIdx.x;
    for (int i = tid; i < 1280; i += 256) {
        int k = i / 20, j = i % 20;
        sw1t[j * 64 + k] = w1[i];
    }
    if (tid < 20) { sb1[tid] = b1[tid]; sw2[tid] = w2[tid]; }
    if (tid == 0) sb2v[0] = b2[0];
    __syncthreads();
    int node = blockIdx.x * 256 + tid;
    if (node >= n) return;
    ull hp[32];
    const float4* r = g_acc2 + (size_t)node * 16;
    #pragma unroll
    for (int i = 0; i < 16; i++) {
        float4 v = r[i];
        hp[2 * i]     = pk2(eluf(v.x), eluf(v.y));
        hp[2 * i + 1] = pk2(eluf(v.z), eluf(v.w));
    }
    uint32_t sbase = smem_u32(sw1t);
    float res = sb2v[0];
    #pragma unroll 2
    for (int j = 0; j < 20; j++) {
        ull a2 = 0;
        uint32_t ra = sbase + (uint32_t)j * 256u;
        #pragma unroll
        for (int kk = 0; kk < 32; kk++) {
            ull w2p = lds_u64(ra + 8u * kk);
            a2 = fma2(hp[kk], w2p, a2);
        }
        float lo, hi; upk2(a2, lo, hi);
        res += eluf(sb1[j] + lo + hi) * sw2[j];
    }
    out[node] = res;
}

// ---------------- host launcher ----------------------------------------------
extern "C" void kernel_launch(void* const* d_in, const int* in_sizes, int n_in,
                              void* d_out, int out_size) {
    const float* x      = (const float*)d_in[0];
    const int*   ei     = (const int*)  d_in[1];
    const float* ea     = (const float*)d_in[2];
    const float* linA_w = (const float*)d_in[3];
    const float* linA_b = (const float*)d_in[4];
    const float* linB_w = (const float*)d_in[5];
    const float* linB_b = (const float*)d_in[6];
    const float* q1_w   = (const float*)d_in[7];
    const float* q1_b   = (const float*)d_in[8];
    const float* k1_w   = (const float*)d_in[9];
    const float* k1_b   = (const float*)d_in[10];
    const float* v1_w   = (const float*)d_in[11];
    const float* v1_b   = (const float*)d_in[12];
    const float* e1_w   = (const float*)d_in[13];
    const float* s1_w   = (const float*)d_in[14];
    const float* s1_b   = (const float*)d_in[15];
    const float* q2_w   = (const float*)d_in[16];
    const float* q2_b   = (const float*)d_in[17];
    const float* k2_w   = (const float*)d_in[18];
    const float* k2_b   = (const float*)d_in[19];
    const float* v2_w   = (const float*)d_in[20];
    const float* v2_b   = (const float*)d_in[21];
    const float* e2_w   = (const float*)d_in[22];
    const float* s2_w   = (const float*)d_in[23];
    const float* s2_b   = (const float*)d_in[24];
    const float* lin1_w = (const float*)d_in[25];
    const float* lin1_b = (const float*)d_in[26];
    const float* lin2_w = (const float*)d_in[27];
    const float* lin2_b = (const float*)d_in[28];

    int n = in_sizes[0] / 23;
    int E = in_sizes[1] / 2;
    const int* src = ei;
    const int* dst = ei + E;
    float* out = (float*)d_out;

    int nb256  = (n + 255) / 256;
    int eb256  = (E + 255) / 256;
    int nbconv = (n + 7) / 8;

    // EXACT R14 configuration (963 us best). k_gemm1 at launch index 3.
    k_zero   <<<nb256, 256>>>(n);
    k_count  <<<eb256, 256>>>(dst, E);
    k_h2     <<<nb256, 256>>>(x, linA_w, linA_b, linB_w, linB_b, n);
    k_gemm1  <<<(n + 127) / 128, 384>>>(q1_w, q1_b, k1_w, k1_b, v1_w, v1_b, s1_w, s1_b, n);
    k_scanA  <<<nb256, 256>>>(n);
    k_scanB  <<<1, 512>>>(nb256);
    k_scanC  <<<nb256, 256>>>(n);
    k_scatter<<<eb256, 256>>>(src, dst, E);
    k_conv1  <<<nbconv, 256>>>(ea, e1_w, n);
    k_gemm2  <<<(n + 63) / 64, 256>>>(q2_w, q2_b, k2_w, k2_b, v2_w, v2_b, s2_w, s2_b, n);
    k_conv2  <<<nbconv, 256>>>(ea, e2_w, n);
    k_final  <<<nb256, 256>>>(lin1_w, lin1_b, lin2_w, lin2_b, out, n);
}

// round 17
// speedup vs baseline: 1.2489x; 1.0344x over previous
#include <cuda_runtime.h>
#include <cuda_bf16.h>
#include <cstdint>

#define NMAX 100000
#define EMAX 800000

typedef unsigned long long ull;

// ---------------- scratch (device globals; no runtime allocation) ------------
__device__ float4 g_h2  [NMAX * 6];        // [N,24] padded (23 + 1 zero)
__device__ float4 g_q1  [NMAX * 48];       // [N,192] fp32, PERMUTED positions
__device__ __nv_bfloat162 g_k1[NMAX * 96]; // [N,192] bf16; slot l+32jj = true ch (tc+2jj, tc+2jj+1)
__device__ __nv_bfloat162 g_v1[NMAX * 96]; // [N,192] bf16; same pairing as k1
__device__ float4 g_acc1[NMAX * 48];       // skip, then conv1 out (pre-elu), TRUE order
__device__ float4 g_q2  [NMAX * 16];       // [N,64] fp32
__device__ float4 g_kv2 [NMAX * 32];       // [N,128]: k | v fp32 linear
__device__ float4 g_acc2[NMAX * 16];       // conv2 out (pre-elu)
// CSR scratch
__device__ int  g_deg   [NMAX];
__device__ int  g_part  [NMAX];
__device__ int  g_bsum  [512];
__device__ int  g_rowptr[NMAX];
__device__ int  g_cursor[NMAX];
__device__ int2 g_cpack [EMAX];            // (src, edge_id) grouped by dst

__device__ __forceinline__ float eluf(float x) { return x > 0.f ? x : expm1f(x); }

// ---- f32x2 packed-math helpers ----------------------------------------------
__device__ __forceinline__ ull pk2(float lo, float hi) {
    ull r; asm("mov.b64 %0,{%1,%2};" : "=l"(r) : "f"(lo), "f"(hi)); return r;
}
__device__ __forceinline__ void upk2(ull v, float& lo, float& hi) {
    asm("mov.b64 {%0,%1},%2;" : "=f"(lo), "=f"(hi) : "l"(v));
}
__device__ __forceinline__ ull fma2(ull a, ull b, ull c) {
    ull d; asm("fma.rn.f32x2 %0,%1,%2,%3;" : "=l"(d) : "l"(a), "l"(b), "l"(c)); return d;
}
__device__ __forceinline__ void lds_v2u64(ull& a, ull& b, uint32_t addr) {
    asm volatile("ld.shared.v2.u64 {%0,%1},[%2];" : "=l"(a), "=l"(b) : "r"(addr));
}
__device__ __forceinline__ ull lds_u64(uint32_t addr) {
    ull a; asm volatile("ld.shared.b64 %0,[%1];" : "=l"(a) : "r"(addr)); return a;
}
__device__ __forceinline__ uint32_t smem_u32(const void* p) {
    uint32_t a;
    asm("{ .reg .u64 t; cvta.to.shared.u64 t, %1; cvt.u32.u64 %0, t; }" : "=r"(a) : "l"(p));
    return a;
}

// ---------------- CSR build ---------------------------------------------------
__global__ void k_zero(int n) {
    int i = blockIdx.x * blockDim.x + threadIdx.x;
    if (i < n) g_deg[i] = 0;
}
__global__ void k_count(const int* __restrict__ dst, int E) {
    int e = blockIdx.x * blockDim.x + threadIdx.x;
    if (e < E) atomicAdd(&g_deg[dst[e]], 1);
}
__global__ void k_scanA(int n) {                 // 256 threads/block
    __shared__ int s[256];
    int tid = threadIdx.x, i = blockIdx.x * 256 + tid;
    int v = (i < n) ? g_deg[i] : 0;
    s[tid] = v; __syncthreads();
    #pragma unroll
    for (int off = 1; off < 256; off <<= 1) {
        int t = (tid >= off) ? s[tid - off] : 0;
        __syncthreads();
        s[tid] += t;
        __syncthreads();
    }
    if (i < n) g_part[i] = s[tid] - v;           // exclusive within block
    if (tid == 255) g_bsum[blockIdx.x] = s[255];
}
__global__ void k_scanB(int nb) {                // single block, 512 threads
    __shared__ int s[512];
    int tid = threadIdx.x;
    int v = (tid < nb) ? g_bsum[tid] : 0;
    s[tid] = v; __syncthreads();
    #pragma unroll
    for (int off = 1; off < 512; off <<= 1) {
        int t = (tid >= off) ? s[tid - off] : 0;
        __syncthreads();
        s[tid] += t;
        __syncthreads();
    }
    g_bsum[tid] = s[tid] - v;                    // exclusive block offsets
}
__global__ void k_scanC(int n) {
    int i = blockIdx.x * blockDim.x + threadIdx.x;
    if (i < n) {
        int r = g_part[i] + g_bsum[i >> 8];
        g_rowptr[i] = r;
        g_cursor[i] = r;
    }
}
__global__ void k_scatter(const int* __restrict__ src, const int* __restrict__ dst, int E) {
    int e = blockIdx.x * blockDim.x + threadIdx.x;
    if (e < E) {
        int d = dst[e];
        int pos = atomicAdd(&g_cursor[d], 1);
        g_cpack[pos] = make_int2(src[e], e);
    }
}

// ---------------- h2 = elu(elu(x@A+bA)@B+bB), padded to 24 -------------------
__global__ void k_h2(const float* __restrict__ x,
                     const float* __restrict__ Aw, const float* __restrict__ Ab,
                     const float* __restrict__ Bw, const float* __restrict__ Bb,
                     int n) {
    __shared__ float sA[23 * 23], sB[23 * 23], sbA[23], sbB[23];
    __shared__ float sx[256 * 23];
    int tid = threadIdx.x;
    for (int i = tid; i < 23 * 23; i += 256) { sA[i] = Aw[i]; sB[i] = Bw[i]; }
    if (tid < 23) { sbA[tid] = Ab[tid]; sbB[tid] = Bb[tid]; }
    int base = blockIdx.x * 256;
    int cnt  = min(256, n - base);
    for (int i = tid; i < cnt * 23; i += 256) sx[i] = x[(size_t)base * 23 + i];
    __syncthreads();
    if (tid < cnt) {
        const float* xr = &sx[tid * 23];
        float h1[23];
        #pragma unroll
        for (int j = 0; j < 23; j++) {
            float a = sbA[j];
            #pragma unroll
            for (int k = 0; k < 23; k++) a += xr[k] * sA[k * 23 + j];
            h1[j] = eluf(a);
        }
        float* out = (float*)g_h2 + (size_t)(base + tid) * 24;
        #pragma unroll
        for (int j = 0; j < 23; j++) {
            float a = sbB[j];
            #pragma unroll
            for (int k = 0; k < 23; k++) a += h1[k] * sB[k * 23 + j];
            out[j] = eluf(a);
        }
        out[23] = 0.f;
    }
}

// ---------------- conv1 node GEMM: [N,24]@[24,768], f32x2, C=2 ---------------
// __launch_bounds__(384,2): profiler-verified win. k AND v stored as packed
// bf16x2 (pair layout: slot l+32jj = true channels (tc+2jj, tc+2jj+1)).
__global__ __launch_bounds__(384, 2) void k_gemm1(
        const float* __restrict__ qw, const float* __restrict__ qb,
        const float* __restrict__ kw, const float* __restrict__ kb,
        const float* __restrict__ vw, const float* __restrict__ vb,
        const float* __restrict__ sw, const float* __restrict__ sb,
        int n) {
    __shared__ float sT[24 * 128];          // transposed [k][node]
    int tid = threadIdx.x;                  // 384 threads
    int base = blockIdx.x * 128;
    int cnt  = min(128, n - base);
    for (int i = tid; i < 768; i += 384) {
        int nn = i & 127, k4 = i >> 7;      // k4 in 0..5
        float4 v = (nn < cnt) ? g_h2[(size_t)(base + nn) * 6 + k4] : make_float4(0, 0, 0, 0);
        sT[(4 * k4 + 0) * 128 + nn] = v.x;
        sT[(4 * k4 + 1) * 128 + nn] = v.y;
        sT[(4 * k4 + 2) * 128 + nn] = v.z;
        sT[(4 * k4 + 3) * 128 + nn] = v.w;
    }
    __syncthreads();
    int arr = tid / 96, pp = tid % 96;
    int l = pp & 31, jj = pp >> 5;
    int p0 = l + 64 * jj, p1 = p0 + 32;
    int cc0, cc1;
    if (arr <= 2) {
        int tc = (l >> 2) * 24 + (l & 3) * 6;
        cc0 = tc + 2 * jj; cc1 = cc0 + 1;
    } else { cc0 = p0; cc1 = p1; }
    const float* W = arr == 0 ? qw : arr == 1 ? kw : arr == 2 ? vw : sw;
    const float* B = arr == 0 ? qb : arr == 1 ? kb : arr == 2 ? vb : sb;
    float* op = arr == 0 ? (float*)g_q1 : (float*)g_acc1;
    __nv_bfloat162* bp = arr == 1 ? g_k1 : g_v1;
    int kslot = l + 32 * jj;
    float w0[23], w1[23];
    #pragma unroll
    for (int k = 0; k < 23; k++) { w0[k] = W[k * 192 + cc0]; w1[k] = W[k * 192 + cc1]; }
    float bias0 = B[cc0], bias1 = B[cc1];
    uint32_t sbase = smem_u32(sT);
    for (int ch = 0; ch < 8; ch++) {
        int n0 = ch * 16;
        ull a0[8], a1[8];
        ull b20 = pk2(bias0, bias0), b21 = pk2(bias1, bias1);
        #pragma unroll
        for (int q8 = 0; q8 < 8; q8++) { a0[q8] = b20; a1[q8] = b21; }
        #pragma unroll
        for (int k = 0; k < 23; k++) {
            ull w20 = pk2(w0[k], w0[k]);
            ull w21 = pk2(w1[k], w1[k]);
            uint32_t ra = sbase + (uint32_t)(k * 128 + n0) * 4u;
            #pragma unroll
            for (int q4 = 0; q4 < 4; q4++) {
                ull h01, h23;
                lds_v2u64(h01, h23, ra + 16u * q4);
                a0[2 * q4]     = fma2(h01, w20, a0[2 * q4]);
                a0[2 * q4 + 1] = fma2(h23, w20, a0[2 * q4 + 1]);
                a1[2 * q4]     = fma2(h01, w21, a1[2 * q4]);
                a1[2 * q4 + 1] = fma2(h23, w21, a1[2 * q4 + 1]);
            }
        }
        #pragma unroll
        for (int q8 = 0; q8 < 8; q8++) {
            float lo0, hi0, lo1, hi1;
            upk2(a0[q8], lo0, hi0);
            upk2(a1[q8], lo1, hi1);
            int na = n0 + 2 * q8, nb = na + 1;
            if (arr == 1 || arr == 2) {
                __nv_bfloat162 ta; ta.x = __float2bfloat16(lo0); ta.y = __float2bfloat16(lo1);
                __nv_bfloat162 tb; tb.x = __float2bfloat16(hi0); tb.y = __float2bfloat16(hi1);
                if (na < cnt) bp[(size_t)(base + na) * 96 + kslot] = ta;
                if (nb < cnt) bp[(size_t)(base + nb) * 96 + kslot] = tb;
            } else {
                if (na < cnt) {
                    op[(size_t)(base + na) * 192 + p0] = lo0;
                    op[(size_t)(base + na) * 192 + p1] = lo1;
                }
                if (nb < cnt) {
                    op[(size_t)(base + nb) * 192 + p0] = hi0;
                    op[(size_t)(base + nb) * 192 + p1] = hi1;
                }
            }
        }
    }
}

// ---------------- conv1: node-centric fused softmax-aggregate -----------------
// k AND v gathered as 3 bf16x2 LDG.32 each; gather working set now ~104 MB,
// fits L2 (126 MB).
__global__ void k_conv1(const float* __restrict__ ea, const float* __restrict__ ew, int n) {
    __shared__ float sW[1344];              // e1_w [7,192] true order
    int tid = threadIdx.x;
    for (int i = tid; i < 1344; i += 256) sW[i] = ew[i];
    __syncthreads();
    int node = blockIdx.x * 8 + (tid >> 5);
    int lane = tid & 31;
    if (node >= n) return;
    int deg = g_deg[node];
    if (deg == 0) return;                   // acc1 already holds skip
    int rs = g_rowptr[node];
    int g = lane & 3;
    int tc = (lane >> 2) * 24 + g * 6;      // true channel base (<= 186)

    const float* qf = (const float*)g_q1 + (size_t)node * 192 + lane;
    float q0 = qf[0],  q1 = qf[32],  q2 = qf[64],
          q3 = qf[96], q4 = qf[128], q5 = qf[160];

    float pqh[7];
    #pragma unroll
    for (int t = 0; t < 7; t++) {
        const float* w = &sW[t * 192 + tc];
        float p = q0 * w[0] + q1 * w[1] + q2 * w[2] + q3 * w[3] + q4 * w[4] + q5 * w[5];
        p += __shfl_xor_sync(0xffffffffu, p, 1);
        p += __shfl_xor_sync(0xffffffffu, p, 2);
        pqh[t] = p;
    }

    float acc0 = 0.f, acc1 = 0.f, acc2 = 0.f, acc3 = 0.f, acc4 = 0.f, acc5 = 0.f;
    float den = 0.f, a0 = 0.f, a1 = 0.f;

    int2 se = g_cpack[rs];
    for (int i = 0; i < deg; i++) {
        int s = se.x, eid = se.y;
        if (i + 1 < deg) se = g_cpack[rs + i + 1];
        float eav[7];
        #pragma unroll
        for (int t = 0; t < 7; t++) eav[t] = __ldg(&ea[(size_t)eid * 7 + t]);
        const __nv_bfloat162* kb = g_k1 + (size_t)s * 96 + lane;
        float2 k01 = __bfloat1622float2(kb[0]);
        float2 k23 = __bfloat1622float2(kb[32]);
        float2 k45 = __bfloat1622float2(kb[64]);
        const __nv_bfloat162* vb = g_v1 + (size_t)s * 96 + lane;
        float2 v01 = __bfloat1622float2(vb[0]);
        float2 v23 = __bfloat1622float2(vb[32]);
        float2 v45 = __bfloat1622float2(vb[64]);
        float lp = q0 * k01.x + q1 * k01.y + q2 * k23.x
                 + q3 * k23.y + q4 * k45.x + q5 * k45.y;
        lp += __shfl_xor_sync(0xffffffffu, lp, 1);
        lp += __shfl_xor_sync(0xffffffffu, lp, 2);
        #pragma unroll
        for (int t = 0; t < 7; t++) lp += eav[t] * pqh[t];
        float ex = __expf(lp * 0.20412414523193154f);   // 1/sqrt(24)
        den += ex;
        acc0 += ex * v01.x; acc1 += ex * v01.y; acc2 += ex * v23.x;
        acc3 += ex * v23.y; acc4 += ex * v45.x; acc5 += ex * v45.y;
        float elo = g == 0 ? eav[0] : g == 1 ? eav[2] : g == 2 ? eav[4] : eav[6];
        float ehi = g == 0 ? eav[1] : g == 1 ? eav[3] : g == 2 ? eav[5] : 0.f;
        a0 += ex * elo;
        a1 += ex * ehi;
    }

    float inv = 1.f / den;
    int base = lane & ~3;
    float ae[7];
    ae[0] = __shfl_sync(0xffffffffu, a0, base);
    ae[1] = __shfl_sync(0xffffffffu, a1, base);
    ae[2] = __shfl_sync(0xffffffffu, a0, base + 1);
    ae[3] = __shfl_sync(0xffffffffu, a1, base + 1);
    ae[4] = __shfl_sync(0xffffffffu, a0, base + 2);
    ae[5] = __shfl_sync(0xffffffffu, a1, base + 2);
    ae[6] = __shfl_sync(0xffffffffu, a0, base + 3);

    float m[6] = {acc0, acc1, acc2, acc3, acc4, acc5};
    const float* wb = &sW[tc];
    #pragma unroll
    for (int j = 0; j < 6; j++) {
        #pragma unroll
        for (int t = 0; t < 7; t++) m[j] += ae[t] * wb[t * 192 + j];
    }
    float* outp = (float*)g_acc1 + (size_t)node * 192 + tc;
    #pragma unroll
    for (int j2 = 0; j2 < 3; j2++) {
        float2 sk = *(float2*)(outp + 2 * j2);
        sk.x += m[2 * j2] * inv;
        sk.y += m[2 * j2 + 1] * inv;
        *(float2*)(outp + 2 * j2) = sk;
    }
}

// ---------------- conv2 node GEMM: elu(acc1) [N,192]@[192,256], f32x2, C=4 ---
__global__ __launch_bounds__(256) void k_gemm2(
        const float* __restrict__ qw, const float* __restrict__ qb,
        const float* __restrict__ kw, const float* __restrict__ kb,
        const float* __restrict__ vw, const float* __restrict__ vb,
        const float* __restrict__ sw, const float* __restrict__ sb,
        int n) {
    __shared__ float sT[192 * 68];          // transposed [k][node], pad 68
    int tid = threadIdx.x;                  // 256 threads
    int base = blockIdx.x * 64;
    int cnt  = min(64, n - base);
    for (int i = tid; i < 64 * 48; i += 256) {
        int nn = i / 48, k4 = i % 48;
        float4 v = (nn < cnt) ? g_acc1[(size_t)(base + nn) * 48 + k4] : make_float4(0, 0, 0, 0);
        v.x = eluf(v.x); v.y = eluf(v.y); v.z = eluf(v.z); v.w = eluf(v.w);
        sT[(4 * k4 + 0) * 68 + nn] = v.x;
        sT[(4 * k4 + 1) * 68 + nn] = v.y;
        sT[(4 * k4 + 2) * 68 + nn] = v.z;
        sT[(4 * k4 + 3) * 68 + nn] = v.w;
    }
    __syncthreads();
    int arr = tid >> 6, u = tid & 63;
    int cq = u & 15, nh = u >> 4;           // nh 0..3 -> nodes nh*16..nh*16+15
    int c0 = 4 * cq;
    const float* W = arr == 0 ? qw : arr == 1 ? kw : arr == 2 ? vw : sw;
    const float* B = arr == 0 ? qb : arr == 1 ? kb : arr == 2 ? vb : sb;
    float* op; int stride; int coff;
    if (arr == 0)      { op = (float*)g_q2;  stride = 64;  coff = c0; }
    else if (arr == 1) { op = (float*)g_kv2; stride = 128; coff = c0; }
    else if (arr == 2) { op = (float*)g_kv2; stride = 128; coff = 64 + c0; }
    else               { op = (float*)g_acc2; stride = 64; coff = c0; }
    ull acc[4][8];
    #pragma unroll
    for (int c = 0; c < 4; c++) {
        float bb = B[c0 + c];
        ull b2 = pk2(bb, bb);
        #pragma unroll
        for (int p = 0; p < 8; p++) acc[c][p] = b2;
    }
    uint32_t sbase = smem_u32(sT);
    #pragma unroll 2
    for (int k = 0; k < 192; k++) {
        float4 w4 = *(const float4*)&W[k * 64 + c0];
        ull w20 = pk2(w4.x, w4.x), w21 = pk2(w4.y, w4.y);
        ull w22 = pk2(w4.z, w4.z), w23 = pk2(w4.w, w4.w);
        uint32_t ra = sbase + (uint32_t)(k * 68 + nh * 16) * 4u;
        ull h[8];
        lds_v2u64(h[0], h[1], ra);
        lds_v2u64(h[2], h[3], ra + 16u);
        lds_v2u64(h[4], h[5], ra + 32u);
        lds_v2u64(h[6], h[7], ra + 48u);
        #pragma unroll
        for (int p = 0; p < 8; p++) {
            acc[0][p] = fma2(h[p], w20, acc[0][p]);
            acc[1][p] = fma2(h[p], w21, acc[1][p]);
            acc[2][p] = fma2(h[p], w22, acc[2][p]);
            acc[3][p] = fma2(h[p], w23, acc[3][p]);
        }
    }
    #pragma unroll
    for (int c = 0; c < 4; c++) {
        #pragma unroll
        for (int p = 0; p < 8; p++) {
            float lo, hi; upk2(acc[c][p], lo, hi);
            int na = nh * 16 + 2 * p, nb = na + 1;
            if (na < cnt) op[(size_t)(base + na) * stride + coff + c] = lo;
            if (nb < cnt) op[(size_t)(base + nb) * stride + coff + c] = hi;
        }
    }
}

// ---------------- conv2: node-centric fused softmax-aggregate (R9 proven) ----
__global__ void k_conv2(const float* __restrict__ ea, const float* __restrict__ ew, int n) {
    __shared__ float sW[448];               // e2_w [7,64]
    int tid = threadIdx.x;
    for (int i = tid; i < 448; i += 256) sW[i] = ew[i];
    __syncthreads();
    int node = blockIdx.x * 8 + (tid >> 5);
    int lane = tid & 31;
    if (node >= n) return;
    int deg = g_deg[node];
    if (deg == 0) return;
    int rs = g_rowptr[node];

    const float* qr = (const float*)g_q2 + (size_t)node * 64 + lane * 2;
    float2 qv = *(const float2*)qr;

    float pqh[7];
    #pragma unroll
    for (int t = 0; t < 7; t++) {
        const float* w = &sW[t * 64 + lane * 2];
        float p = qv.x * w[0] + qv.y * w[1];
        p += __shfl_xor_sync(0xffffffffu, p, 1);
        p += __shfl_xor_sync(0xffffffffu, p, 2);
        pqh[t] = p;
    }

    float acc0 = 0.f, acc1 = 0.f, den = 0.f, a0 = 0.f, a1 = 0.f;
    int g = lane & 3;

    int2 se = g_cpack[rs];
    for (int i = 0; i < deg; i++) {
        int s = se.x, eid = se.y;
        if (i + 1 < deg) se = g_cpack[rs + i + 1];
        float eav[7];
        #pragma unroll
        for (int t = 0; t < 7; t++) eav[t] = __ldg(&ea[(size_t)eid * 7 + t]);
        const float* kv = (const float*)g_kv2 + (size_t)s * 128 + lane * 2;
        float2 kk = *(const float2*)kv;
        float2 vv = *(const float2*)(kv + 64);
        float lp = qv.x * kk.x + qv.y * kk.y;
        lp += __shfl_xor_sync(0xffffffffu, lp, 1);
        lp += __shfl_xor_sync(0xffffffffu, lp, 2);
        #pragma unroll
        for (int t = 0; t < 7; t++) lp += eav[t] * pqh[t];
        float ex = __expf(lp * 0.35355339059327373f);   // 1/sqrt(8)
        den += ex;
        acc0 += ex * vv.x;
        acc1 += ex * vv.y;
        float elo = g == 0 ? eav[0] : g == 1 ? eav[2] : g == 2 ? eav[4] : eav[6];
        float ehi = g == 0 ? eav[1] : g == 1 ? eav[3] : g == 2 ? eav[5] : 0.f;
        a0 += ex * elo;
        a1 += ex * ehi;
    }

    float inv = 1.f / den;
    int base = lane & ~3;
    float ae[7];
    ae[0] = __shfl_sync(0xffffffffu, a0, base);
    ae[1] = __shfl_sync(0xffffffffu, a1, base);
    ae[2] = __shfl_sync(0xffffffffu, a0, base + 1);
    ae[3] = __shfl_sync(0xffffffffu, a1, base + 1);
    ae[4] = __shfl_sync(0xffffffffu, a0, base + 2);
    ae[5] = __shfl_sync(0xffffffffu, a1, base + 2);
    ae[6] = __shfl_sync(0xffffffffu, a0, base + 3);

    float m0 = acc0, m1 = acc1;
    const float* wb = &sW[lane * 2];
    #pragma unroll
    for (int t = 0; t < 7; t++) {
        m0 += ae[t] * wb[t * 64];
        m1 += ae[t] * wb[t * 64 + 1];
    }
    float* outp = (float*)g_acc2 + (size_t)node * 64 + lane * 2;
    float2 sk = *(float2*)outp;
    sk.x += m0 * inv;
    sk.y += m1 * inv;
    *(float2*)outp = sk;
}

// ---------------- head: elu -> lin1(64,20) -> elu -> lin2(20,1), f32x2 -------
__global__ void k_final(const float* __restrict__ w1, const float* __restrict__ b1,
                        const float* __restrict__ w2, const float* __restrict__ b2,
                        float* __restrict__ out, int n) {
    __shared__ float sw1t[20 * 64];         // transposed [j][k]
    __shared__ float sb1[20], sw2[20], sb2v[1];
    int tid = threadIdx.x;
    for (int i = tid; i < 1280; i += 256) {
        int k = i / 20, j = i % 20;
        sw1t[j * 64 + k] = w1[i];
    }
    if (tid < 20) { sb1[tid] = b1[tid]; sw2[tid] = w2[tid]; }
    if (tid == 0) sb2v[0] = b2[0];
    __syncthreads();
    int node = blockIdx.x * 256 + tid;
    if (node >= n) return;
    ull hp[32];
    const float4* r = g_acc2 + (size_t)node * 16;
    #pragma unroll
    for (int i = 0; i < 16; i++) {
        float4 v = r[i];
        hp[2 * i]     = pk2(eluf(v.x), eluf(v.y));
        hp[2 * i + 1] = pk2(eluf(v.z), eluf(v.w));
    }
    uint32_t sbase = smem_u32(sw1t);
    float res = sb2v[0];
    #pragma unroll 2
    for (int j = 0; j < 20; j++) {
        ull a2 = 0;
        uint32_t ra = sbase + (uint32_t)j * 256u;
        #pragma unroll
        for (int kk = 0; kk < 32; kk++) {
            ull w2p = lds_u64(ra + 8u * kk);
            a2 = fma2(hp[kk], w2p, a2);
        }
        float lo, hi; upk2(a2, lo, hi);
        res += eluf(sb1[j] + lo + hi) * sw2[j];
    }
    out[node] = res;
}

// ---------------- host launcher ----------------------------------------------
extern "C" void kernel_launch(void* const* d_in, const int* in_sizes, int n_in,
                              void* d_out, int out_size) {
    const float* x      = (const float*)d_in[0];
    const int*   ei     = (const int*)  d_in[1];
    const float* ea     = (const float*)d_in[2];
    const float* linA_w = (const float*)d_in[3];
    const float* linA_b = (const float*)d_in[4];
    const float* linB_w = (const float*)d_in[5];
    const float* linB_b = (const float*)d_in[6];
    const float* q1_w   = (const float*)d_in[7];
    const float* q1_b   = (const float*)d_in[8];
    const float* k1_w   = (const float*)d_in[9];
    const float* k1_b   = (const float*)d_in[10];
    const float* v1_w   = (const float*)d_in[11];
    const float* v1_b   = (const float*)d_in[12];
    const float* e1_w   = (const float*)d_in[13];
    const float* s1_w   = (const float*)d_in[14];
    const float* s1_b   = (const float*)d_in[15];
    const float* q2_w   = (const float*)d_in[16];
    const float* q2_b   = (const float*)d_in[17];
    const float* k2_w   = (const float*)d_in[18];
    const float* k2_b   = (const float*)d_in[19];
    const float* v2_w   = (const float*)d_in[20];
    const float* v2_b   = (const float*)d_in[21];
    const float* e2_w   = (const float*)d_in[22];
    const float* s2_w   = (const float*)d_in[23];
    const float* s2_b   = (const float*)d_in[24];
    const float* lin1_w = (const float*)d_in[25];
    const float* lin1_b = (const float*)d_in[26];
    const float* lin2_w = (const float*)d_in[27];
    const float* lin2_b = (const float*)d_in[28];

    int n = in_sizes[0] / 23;
    int E = in_sizes[1] / 2;
    const int* src = ei;
    const int* dst = ei + E;
    float* out = (float*)d_out;

    int nb256  = (n + 255) / 256;
    int eb256  = (E + 255) / 256;
    int nbconv = (n + 7) / 8;

    // EXACT R14/R16 launch order (963 us, reproduced twice).
    k_zero   <<<nb256, 256>>>(n);
    k_count  <<<eb256, 256>>>(dst, E);
    k_h2     <<<nb256, 256>>>(x, linA_w, linA_b, linB_w, linB_b, n);
    k_gemm1  <<<(n + 127) / 128, 384>>>(q1_w, q1_b, k1_w, k1_b, v1_w, v1_b, s1_w, s1_b, n);
    k_scanA  <<<nb256, 256>>>(n);
    k_scanB  <<<1, 512>>>(nb256);
    k_scanC  <<<nb256, 256>>>(n);
    k_scatter<<<eb256, 256>>>(src, dst, E);
    k_conv1  <<<nbconv, 256>>>(ea, e1_w, n);
    k_gemm2  <<<(n + 63) / 64, 256>>>(q2_w, q2_b, k2_w, k2_b, v2_w, v2_b, s2_w, s2_b, n);
    k_conv2  <<<nbconv, 256>>>(ea, e2_w, n);
    k_final  <<<nb256, 256>>>(lin1_w, lin1_b, lin2_w, lin2_b, out, n);
}